// round 14
// baseline (speedup 1.0000x reference)
#include <cuda_runtime.h>
#include <cstdint>

#define DIM 2048
#define NH 16
#define HD 128
#define BATCH 2
#define SEQ 2048
#define ROWS_TOT (BATCH*SEQ)   // 4096

// ---------------- scratch (device globals: the sanctioned no-alloc workaround) ----
__device__ float g_Xc [(size_t)ROWS_TOT*DIM];
__device__ float g_WqT[(size_t)DIM*DIM];
__device__ float g_WkT[(size_t)DIM*DIM];
__device__ float g_WvT[(size_t)DIM*DIM];
__device__ float g_WoT[(size_t)DIM*DIM];
__device__ float g_Q  [(size_t)ROWS_TOT*DIM];
__device__ float g_Km [(size_t)ROWS_TOT*DIM];
__device__ float g_V  [(size_t)ROWS_TOT*DIM];
__device__ float g_Vt [(size_t)BATCH*NH*HD*SEQ];
__device__ float g_P  [(size_t)BATCH*NH*SEQ*SEQ];   // 512 MB scores/probs
__device__ float g_O  [(size_t)ROWS_TOT*DIM];

// ---------------- helpers ----------------
__device__ __forceinline__ float rna_tf32(float x){
    uint32_t u; asm("cvt.rna.tf32.f32 %0, %1;" : "=r"(u) : "f"(x));
    return __uint_as_float(u);
}
__device__ __forceinline__ void cp16(uint32_t saddr, const void* g){
    asm volatile("cp.async.cg.shared.global [%0], [%1], 16;\n" :: "r"(saddr), "l"(g));
}

// ---------------- generic batched NT GEMM, tf32 mma ----------------
// C[m,n] = alpha * sum_k A[m,k]*B[n,k]; A,B,C row-major with ld strides.
// z = blockIdx.z -> (b = z/H, h = z%H); per-(b,h) base offsets via strides.
// Block tile 128x128, BK=32, 256 threads (8 warps of 64x32), cp.async 2-stage.
template<bool RND>
__global__ void __launch_bounds__(256)
gemm_nt(const float* __restrict__ Ag, const float* __restrict__ Bg,
        float* __restrict__ Cg,
        int K, int lda, int ldb, int ldc,
        int H, long long sAh, long long sAb,
        long long sBh, long long sBb,
        long long sCh, long long sCb, float alpha)
{
    extern __shared__ float smem[];   // 2 stages * (128*36 A + 128*36 B) floats
    const int tid = threadIdx.x;
    const int z  = blockIdx.z;
    const int zb = z / H, zh = z - zb*H;
    const float* A = Ag + (long long)zb*sAb + (long long)zh*sAh;
    const float* B = Bg + (long long)zb*sBb + (long long)zh*sBh;
    float*       C = Cg + (long long)zb*sCb + (long long)zh*sCh;
    const int m0 = blockIdx.y * 128;
    const int n0 = blockIdx.x * 128;

    auto load_stage = [&](int stage, int k0){
        uint32_t sb = (uint32_t)__cvta_generic_to_shared(smem + stage*9216);
        #pragma unroll
        for (int i=0;i<4;i++){
            int f = tid + i*256;
            int row = f >> 3, c4 = (f & 7) << 2;
            cp16(sb + (uint32_t)(row*36 + c4)*4u,
                 A + (long long)(m0+row)*lda + k0 + c4);
        }
        uint32_t sbB = sb + 4608u*4u;
        #pragma unroll
        for (int i=0;i<4;i++){
            int f = tid + i*256;
            int row = f >> 3, c4 = (f & 7) << 2;
            cp16(sbB + (uint32_t)(row*36 + c4)*4u,
                 B + (long long)(n0+row)*ldb + k0 + c4);
        }
    };

    float acc[4][4][4];
    #pragma unroll
    for (int a=0;a<4;a++)
      #pragma unroll
      for (int b=0;b<4;b++)
        #pragma unroll
        for (int c=0;c<4;c++) acc[a][b][c] = 0.f;

    const int wid = tid >> 5, lane = tid & 31;
    const int wm = (wid & 1) * 64, wn = (wid >> 1) * 32;
    const int gid = lane >> 2, tg = lane & 3;

    const int KT = K >> 5;
    load_stage(0, 0);
    asm volatile("cp.async.commit_group;\n");

    for (int kt=0; kt<KT; ++kt){
        if (kt+1 < KT){
            load_stage((kt+1)&1, (kt+1) << 5);
            asm volatile("cp.async.commit_group;\n");
            asm volatile("cp.async.wait_group 1;\n");
        } else {
            asm volatile("cp.async.wait_group 0;\n");
        }
        __syncthreads();
        const float* As = smem + (kt&1)*9216;
        const float* Bs = As + 4608;
        #pragma unroll
        for (int ks=0; ks<4; ks++){
            const int k8 = ks*8;
            uint32_t af[4][4], bf[4][2];
            #pragma unroll
            for (int im=0; im<4; im++){
                int r = wm + im*16 + gid;
                af[im][0] = __float_as_uint(As[ r     *36 + k8 + tg    ]);
                af[im][1] = __float_as_uint(As[(r+8)  *36 + k8 + tg    ]);
                af[im][2] = __float_as_uint(As[ r     *36 + k8 + tg + 4]);
                af[im][3] = __float_as_uint(As[(r+8)  *36 + k8 + tg + 4]);
            }
            #pragma unroll
            for (int jn=0; jn<4; jn++){
                int nn = wn + jn*8 + gid;
                bf[jn][0] = __float_as_uint(Bs[nn*36 + k8 + tg    ]);
                bf[jn][1] = __float_as_uint(Bs[nn*36 + k8 + tg + 4]);
            }
            #pragma unroll
            for (int im=0; im<4; im++)
              #pragma unroll
              for (int jn=0; jn<4; jn++)
                asm volatile(
                  "mma.sync.aligned.m16n8k8.row.col.f32.tf32.tf32.f32 "
                  "{%0,%1,%2,%3}, {%4,%5,%6,%7}, {%8,%9}, {%0,%1,%2,%3};"
                  : "+f"(acc[im][jn][0]), "+f"(acc[im][jn][1]),
                    "+f"(acc[im][jn][2]), "+f"(acc[im][jn][3])
                  : "r"(af[im][0]), "r"(af[im][1]), "r"(af[im][2]), "r"(af[im][3]),
                    "r"(bf[jn][0]), "r"(bf[jn][1]));
        }
        __syncthreads();
    }

    #pragma unroll
    for (int im=0; im<4; im++){
        #pragma unroll
        for (int jn=0; jn<4; jn++){
            long long r0 = m0 + wm + im*16 + gid;
            int cc = n0 + wn + jn*8 + tg*2;
            float v0 = acc[im][jn][0]*alpha, v1 = acc[im][jn][1]*alpha;
            float v2 = acc[im][jn][2]*alpha, v3 = acc[im][jn][3]*alpha;
            if (RND){ v0=rna_tf32(v0); v1=rna_tf32(v1); v2=rna_tf32(v2); v3=rna_tf32(v3); }
            *(float2*)&C[ r0   *ldc + cc] = make_float2(v0, v1);
            *(float2*)&C[(r0+8)*ldc + cc] = make_float2(v2, v3);
        }
    }
}

// ---------------- row softmax (2048 cols), output rounded to tf32 grid ----------
__global__ void softmax_rows_rna(float* __restrict__ P){
    const int n = 2048;
    long long row = blockIdx.x;
    float* p = P + row * (long long)n;
    int tid = threadIdx.x;   // 256
    float v[8];
    float m = -3.0e38f;
    #pragma unroll
    for (int i=0;i<8;i++){ v[i] = p[tid + i*256]; m = fmaxf(m, v[i]); }
    #pragma unroll
    for (int o=16;o;o>>=1) m = fmaxf(m, __shfl_xor_sync(0xffffffffu, m, o));
    __shared__ float red[8];
    if ((tid&31)==0) red[tid>>5] = m;
    __syncthreads();
    float bm = red[0];
    #pragma unroll
    for (int i=1;i<8;i++) bm = fmaxf(bm, red[i]);
    float s = 0.f;
    #pragma unroll
    for (int i=0;i<8;i++){ v[i] = __expf(v[i]-bm); s += v[i]; }
    #pragma unroll
    for (int o=16;o;o>>=1) s += __shfl_xor_sync(0xffffffffu, s, o);
    __syncthreads();
    if ((tid&31)==0) red[tid>>5] = s;
    __syncthreads();
    float bs = 0.f;
    #pragma unroll
    for (int i=0;i<8;i++) bs += red[i];
    float inv = 1.0f / bs;
    #pragma unroll
    for (int i=0;i<8;i++) p[tid + i*256] = rna_tf32(v[i]*inv);
}

// ---------------- tiled transpose (optionally rounding to tf32 grid) -----------
__global__ void transpose_z(const float* __restrict__ In, float* __restrict__ Out,
                            int lda, int ldo, int H,
                            long long siH, long long siB,
                            long long soH, long long soB, int doRnd)
{
    __shared__ float tile[32][33];
    int z = blockIdx.z, b = z / H, h = z - b*H;
    const float* in = In + (long long)b*siB + (long long)h*siH;
    float* out      = Out + (long long)b*soB + (long long)h*soH;
    int c0 = blockIdx.x*32, r0 = blockIdx.y*32;
    int tx = threadIdx.x, ty = threadIdx.y;   // 32 x 8
    #pragma unroll
    for (int i=0;i<32;i+=8)
        tile[ty+i][tx] = in[(long long)(r0+ty+i)*lda + c0+tx];
    __syncthreads();
    #pragma unroll
    for (int i=0;i<32;i+=8){
        float vv = tile[tx][ty+i];
        out[(long long)(c0+ty+i)*ldo + r0+tx] = doRnd ? rna_tf32(vv) : vv;
    }
}

// ---------------- rounded copy ----------------
__global__ void rna_copy(const float* __restrict__ in, float* __restrict__ out, long long n){
    long long i = (long long)blockIdx.x*blockDim.x + threadIdx.x;
    if (i < n) out[i] = rna_tf32(in[i]);
}

// ---------------- driver ----------------
extern "C" void kernel_launch(void* const* d_in, const int* in_sizes, int n_in,
                              void* d_out, int out_size)
{
    (void)in_sizes; (void)n_in; (void)out_size;
    const float* x  = (const float*)d_in[0];
    const float* Wq = (const float*)d_in[1];
    const float* Wk = (const float*)d_in[2];
    const float* Wv = (const float*)d_in[3];
    const float* Wo = (const float*)d_in[4];
    float* Y = (float*)d_out;

    float *Xc,*WqT,*WkT,*WvT,*WoT,*Q,*Kм,*V,*Vt,*P,*O;
    cudaGetSymbolAddress((void**)&Xc,  g_Xc);
    cudaGetSymbolAddress((void**)&WqT, g_WqT);
    cudaGetSymbolAddress((void**)&WkT, g_WkT);
    cudaGetSymbolAddress((void**)&WvT, g_WvT);
    cudaGetSymbolAddress((void**)&WoT, g_WoT);
    cudaGetSymbolAddress((void**)&Q,   g_Q);
    cudaGetSymbolAddress((void**)&Kм,  g_Km);
    cudaGetSymbolAddress((void**)&V,   g_V);
    cudaGetSymbolAddress((void**)&Vt,  g_Vt);
    cudaGetSymbolAddress((void**)&P,   g_P);
    cudaGetSymbolAddress((void**)&O,   g_O);

    const int SMB = 73728;  // 2 stages * (128*36*2 tiles) * 4B
    cudaFuncSetAttribute(gemm_nt<true>,  cudaFuncAttributeMaxDynamicSharedMemorySize, SMB);
    cudaFuncSetAttribute(gemm_nt<false>, cudaFuncAttributeMaxDynamicSharedMemorySize, SMB);

    const long long nX = (long long)ROWS_TOT*DIM;
    rna_copy<<<(int)((nX+255)/256), 256>>>(x, Xc, nX);

    dim3 tb(32,8);
    dim3 tgW(DIM/32, DIM/32, 1);
    transpose_z<<<tgW, tb>>>(Wq, WqT, DIM, DIM, 1, 0,0,0,0, 1);
    transpose_z<<<tgW, tb>>>(Wk, WkT, DIM, DIM, 1, 0,0,0,0, 1);
    transpose_z<<<tgW, tb>>>(Wv, WvT, DIM, DIM, 1, 0,0,0,0, 1);
    transpose_z<<<tgW, tb>>>(Wo, WoT, DIM, DIM, 1, 0,0,0,0, 1);

    // QKV projections: [4096,2048] = Xc @ W^T(NT)
    dim3 gg(DIM/128, ROWS_TOT/128, 1);
    gemm_nt<true ><<<gg, 256, SMB>>>(Xc, WqT, Q,  DIM, DIM, DIM, DIM, 1, 0,0, 0,0, 0,0, 1.0f);
    gemm_nt<true ><<<gg, 256, SMB>>>(Xc, WkT, Kм, DIM, DIM, DIM, DIM, 1, 0,0, 0,0, 0,0, 1.0f);
    gemm_nt<true ><<<gg, 256, SMB>>>(Xc, WvT, V,  DIM, DIM, DIM, DIM, 1, 0,0, 0,0, 0,0, 1.0f);

    // V -> Vt  [b,h,d,s]
    dim3 tgV(HD/32, SEQ/32, BATCH*NH);
    transpose_z<<<tgV, tb>>>(V, Vt, DIM, SEQ, NH,
                             (long long)HD, (long long)SEQ*DIM,
                             (long long)HD*SEQ, (long long)NH*HD*SEQ, 0);

    // scores: per (b,h)  P[2048,2048] = Q_bh @ K_bh^T * scale
    dim3 gs(SEQ/128, SEQ/128, BATCH*NH);
    gemm_nt<false><<<gs, 256, SMB>>>(Q, Kм, P, HD, DIM, DIM, SEQ,
        NH, (long long)HD, (long long)SEQ*DIM,
            (long long)HD, (long long)SEQ*DIM,
        (long long)SEQ*SEQ, (long long)NH*(long long)SEQ*SEQ,
        0.08838834764831845f /* 1/sqrt(128) */);

    softmax_rows_rna<<<BATCH*NH*SEQ, 256>>>(P);

    // PV: per (b,h)  O_bh[2048,128] = P_bh @ Vt_bh^T(NT)
    dim3 gpv(HD/128, SEQ/128, BATCH*NH);
    gemm_nt<true ><<<gpv, 256, SMB>>>(P, Vt, O, SEQ, SEQ, SEQ, DIM,
        NH, (long long)SEQ*SEQ, (long long)NH*(long long)SEQ*SEQ,
            (long long)HD*SEQ,  (long long)NH*HD*SEQ,
            (long long)HD,      (long long)SEQ*DIM,
        1.0f);

    // out projection: Y = O @ Wo^T(NT)
    gemm_nt<false><<<gg, 256, SMB>>>(O, WoT, Y, DIM, DIM, DIM, DIM, 1, 0,0, 0,0, 0,0, 1.0f);
}

// round 15
// speedup vs baseline: 1.0010x; 1.0010x over previous
#include <cuda_runtime.h>
#include <cstdint>

#define DIM 2048
#define NH 16
#define HD 128
#define BATCH 2
#define SEQ 2048
#define ROWS_TOT (BATCH*SEQ)   // 4096

// ---------------- scratch (device globals: the sanctioned no-alloc workaround) ----
__device__ float g_Xc [(size_t)ROWS_TOT*DIM];
__device__ float g_WqT[(size_t)DIM*DIM];
__device__ float g_WkT[(size_t)DIM*DIM];
__device__ float g_WvT[(size_t)DIM*DIM];
__device__ float g_WoT[(size_t)DIM*DIM];
__device__ float g_Q  [(size_t)ROWS_TOT*DIM];
__device__ float g_Km [(size_t)ROWS_TOT*DIM];
__device__ float g_V  [(size_t)ROWS_TOT*DIM];
__device__ float g_Vt [(size_t)BATCH*NH*HD*SEQ];
__device__ float g_P  [(size_t)BATCH*NH*SEQ*SEQ];   // 512 MB scores/probs
__device__ float g_O  [(size_t)ROWS_TOT*DIM];

// ---------------- helpers ----------------
__device__ __forceinline__ float rna_tf32(float x){
    uint32_t u; asm("cvt.rna.tf32.f32 %0, %1;" : "=r"(u) : "f"(x));
    return __uint_as_float(u);
}
__device__ __forceinline__ void cp16(uint32_t saddr, const void* g){
    asm volatile("cp.async.cg.shared.global [%0], [%1], 16;\n" :: "r"(saddr), "l"(g));
}

// ---------------- generic batched NT GEMM, tf32 mma ----------------
// C[m,n] = alpha * sum_k A[m,k]*B[n,k]; A,B,C row-major with ld strides.
// z = blockIdx.z -> (b = z/H, h = z%H); per-(b,h) base offsets via strides.
// Block tile 128x128, BK=32, 256 threads (8 warps of 64x32), cp.async 2-stage.
template<bool RND>
__global__ void __launch_bounds__(256)
gemm_nt(const float* __restrict__ Ag, const float* __restrict__ Bg,
        float* __restrict__ Cg,
        int K, int lda, int ldb, int ldc,
        int H, long long sAh, long long sAb,
        long long sBh, long long sBb,
        long long sCh, long long sCb, float alpha)
{
    extern __shared__ float smem[];   // 2 stages * (128*36 A + 128*36 B) floats
    const int tid = threadIdx.x;
    const int z  = blockIdx.z;
    const int zb = z / H, zh = z - zb*H;
    const float* A = Ag + (long long)zb*sAb + (long long)zh*sAh;
    const float* B = Bg + (long long)zb*sBb + (long long)zh*sBh;
    float*       C = Cg + (long long)zb*sCb + (long long)zh*sCh;
    const int m0 = blockIdx.y * 128;
    const int n0 = blockIdx.x * 128;

    auto load_stage = [&](int stage, int k0){
        uint32_t sb = (uint32_t)__cvta_generic_to_shared(smem + stage*9216);
        #pragma unroll
        for (int i=0;i<4;i++){
            int f = tid + i*256;
            int row = f >> 3, c4 = (f & 7) << 2;
            cp16(sb + (uint32_t)(row*36 + c4)*4u,
                 A + (long long)(m0+row)*lda + k0 + c4);
        }
        uint32_t sbB = sb + 4608u*4u;
        #pragma unroll
        for (int i=0;i<4;i++){
            int f = tid + i*256;
            int row = f >> 3, c4 = (f & 7) << 2;
            cp16(sbB + (uint32_t)(row*36 + c4)*4u,
                 B + (long long)(n0+row)*ldb + k0 + c4);
        }
    };

    float acc[4][4][4];
    #pragma unroll
    for (int a=0;a<4;a++)
      #pragma unroll
      for (int b=0;b<4;b++)
        #pragma unroll
        for (int c=0;c<4;c++) acc[a][b][c] = 0.f;

    const int wid = tid >> 5, lane = tid & 31;
    const int wm = (wid & 1) * 64, wn = (wid >> 1) * 32;
    const int gid = lane >> 2, tg = lane & 3;

    const int KT = K >> 5;
    load_stage(0, 0);
    asm volatile("cp.async.commit_group;\n");

    for (int kt=0; kt<KT; ++kt){
        if (kt+1 < KT){
            load_stage((kt+1)&1, (kt+1) << 5);
            asm volatile("cp.async.commit_group;\n");
            asm volatile("cp.async.wait_group 1;\n");
        } else {
            asm volatile("cp.async.wait_group 0;\n");
        }
        __syncthreads();
        const float* As = smem + (kt&1)*9216;
        const float* Bs = As + 4608;
        #pragma unroll
        for (int ks=0; ks<4; ks++){
            const int k8 = ks*8;
            uint32_t af[4][4], bf[4][2];
            #pragma unroll
            for (int im=0; im<4; im++){
                int r = wm + im*16 + gid;
                af[im][0] = __float_as_uint(As[ r     *36 + k8 + tg    ]);
                af[im][1] = __float_as_uint(As[(r+8)  *36 + k8 + tg    ]);
                af[im][2] = __float_as_uint(As[ r     *36 + k8 + tg + 4]);
                af[im][3] = __float_as_uint(As[(r+8)  *36 + k8 + tg + 4]);
            }
            #pragma unroll
            for (int jn=0; jn<4; jn++){
                int nn = wn + jn*8 + gid;
                bf[jn][0] = __float_as_uint(Bs[nn*36 + k8 + tg    ]);
                bf[jn][1] = __float_as_uint(Bs[nn*36 + k8 + tg + 4]);
            }
            #pragma unroll
            for (int im=0; im<4; im++)
              #pragma unroll
              for (int jn=0; jn<4; jn++)
                asm volatile(
                  "mma.sync.aligned.m16n8k8.row.col.f32.tf32.tf32.f32 "
                  "{%0,%1,%2,%3}, {%4,%5,%6,%7}, {%8,%9}, {%0,%1,%2,%3};"
                  : "+f"(acc[im][jn][0]), "+f"(acc[im][jn][1]),
                    "+f"(acc[im][jn][2]), "+f"(acc[im][jn][3])
                  : "r"(af[im][0]), "r"(af[im][1]), "r"(af[im][2]), "r"(af[im][3]),
                    "r"(bf[jn][0]), "r"(bf[jn][1]));
        }
        __syncthreads();
    }

    #pragma unroll
    for (int im=0; im<4; im++){
        #pragma unroll
        for (int jn=0; jn<4; jn++){
            long long r0 = m0 + wm + im*16 + gid;
            int cc = n0 + wn + jn*8 + tg*2;
            float v0 = acc[im][jn][0]*alpha, v1 = acc[im][jn][1]*alpha;
            float v2 = acc[im][jn][2]*alpha, v3 = acc[im][jn][3]*alpha;
            if (RND){ v0=rna_tf32(v0); v1=rna_tf32(v1); v2=rna_tf32(v2); v3=rna_tf32(v3); }
            *(float2*)&C[ r0   *ldc + cc] = make_float2(v0, v1);
            *(float2*)&C[(r0+8)*ldc + cc] = make_float2(v2, v3);
        }
    }
}

// ---------------- row softmax (2048 cols), output rounded to tf32 grid ----------
__global__ void softmax_rows_rna(float* __restrict__ P){
    const int n = 2048;
    long long row = blockIdx.x;
    float* p = P + row * (long long)n;
    int tid = threadIdx.x;   // 256
    float v[8];
    float m = -3.0e38f;
    #pragma unroll
    for (int i=0;i<8;i++){ v[i] = p[tid + i*256]; m = fmaxf(m, v[i]); }
    #pragma unroll
    for (int o=16;o;o>>=1) m = fmaxf(m, __shfl_xor_sync(0xffffffffu, m, o));
    __shared__ float red[8];
    if ((tid&31)==0) red[tid>>5] = m;
    __syncthreads();
    float bm = red[0];
    #pragma unroll
    for (int i=1;i<8;i++) bm = fmaxf(bm, red[i]);
    float s = 0.f;
    #pragma unroll
    for (int i=0;i<8;i++){ v[i] = __expf(v[i]-bm); s += v[i]; }
    #pragma unroll
    for (int o=16;o;o>>=1) s += __shfl_xor_sync(0xffffffffu, s, o);
    __syncthreads();
    if ((tid&31)==0) red[tid>>5] = s;
    __syncthreads();
    float bs = 0.f;
    #pragma unroll
    for (int i=0;i<8;i++) bs += red[i];
    float inv = 1.0f / bs;
    #pragma unroll
    for (int i=0;i<8;i++) p[tid + i*256] = rna_tf32(v[i]*inv);
}

// ---------------- tiled transpose (optionally rounding to tf32 grid) -----------
__global__ void transpose_z(const float* __restrict__ In, float* __restrict__ Out,
                            int lda, int ldo, int H,
                            long long siH, long long siB,
                            long long soH, long long soB, int doRnd)
{
    __shared__ float tile[32][33];
    int z = blockIdx.z, b = z / H, h = z - b*H;
    const float* in = In + (long long)b*siB + (long long)h*siH;
    float* out      = Out + (long long)b*soB + (long long)h*soH;
    int c0 = blockIdx.x*32, r0 = blockIdx.y*32;
    int tx = threadIdx.x, ty = threadIdx.y;   // 32 x 8
    #pragma unroll
    for (int i=0;i<32;i+=8)
        tile[ty+i][tx] = in[(long long)(r0+ty+i)*lda + c0+tx];
    __syncthreads();
    #pragma unroll
    for (int i=0;i<32;i+=8){
        float vv = tile[tx][ty+i];
        out[(long long)(c0+ty+i)*ldo + r0+tx] = doRnd ? rna_tf32(vv) : vv;
    }
}

// ---------------- rounded copy ----------------
__global__ void rna_copy(const float* __restrict__ in, float* __restrict__ out, long long n){
    long long i = (long long)blockIdx.x*blockDim.x + threadIdx.x;
    if (i < n) out[i] = rna_tf32(in[i]);
}

// ---------------- driver ----------------
extern "C" void kernel_launch(void* const* d_in, const int* in_sizes, int n_in,
                              void* d_out, int out_size)
{
    (void)in_sizes; (void)n_in; (void)out_size;
    const float* x  = (const float*)d_in[0];
    const float* Wq = (const float*)d_in[1];
    const float* Wk = (const float*)d_in[2];
    const float* Wv = (const float*)d_in[3];
    const float* Wo = (const float*)d_in[4];
    float* Y = (float*)d_out;

    float *Xc,*WqT,*WkT,*WvT,*WoT,*Q,*Kм,*V,*Vt,*P,*O;
    cudaGetSymbolAddress((void**)&Xc,  g_Xc);
    cudaGetSymbolAddress((void**)&WqT, g_WqT);
    cudaGetSymbolAddress((void**)&WkT, g_WkT);
    cudaGetSymbolAddress((void**)&WvT, g_WvT);
    cudaGetSymbolAddress((void**)&WoT, g_WoT);
    cudaGetSymbolAddress((void**)&Q,   g_Q);
    cudaGetSymbolAddress((void**)&Kм,  g_Km);
    cudaGetSymbolAddress((void**)&V,   g_V);
    cudaGetSymbolAddress((void**)&Vt,  g_Vt);
    cudaGetSymbolAddress((void**)&P,   g_P);
    cudaGetSymbolAddress((void**)&O,   g_O);

    const int SMB = 73728;  // 2 stages * (128*36*2 tiles) * 4B
    cudaFuncSetAttribute(gemm_nt<true>,  cudaFuncAttributeMaxDynamicSharedMemorySize, SMB);
    cudaFuncSetAttribute(gemm_nt<false>, cudaFuncAttributeMaxDynamicSharedMemorySize, SMB);

    const long long nX = (long long)ROWS_TOT*DIM;
    rna_copy<<<(int)((nX+255)/256), 256>>>(x, Xc, nX);

    dim3 tb(32,8);
    dim3 tgW(DIM/32, DIM/32, 1);
    transpose_z<<<tgW, tb>>>(Wq, WqT, DIM, DIM, 1, 0,0,0,0, 1);
    transpose_z<<<tgW, tb>>>(Wk, WkT, DIM, DIM, 1, 0,0,0,0, 1);
    transpose_z<<<tgW, tb>>>(Wv, WvT, DIM, DIM, 1, 0,0,0,0, 1);
    transpose_z<<<tgW, tb>>>(Wo, WoT, DIM, DIM, 1, 0,0,0,0, 1);

    // QKV projections: [4096,2048] = Xc @ W^T(NT)
    dim3 gg(DIM/128, ROWS_TOT/128, 1);
    gemm_nt<true ><<<gg, 256, SMB>>>(Xc, WqT, Q,  DIM, DIM, DIM, DIM, 1, 0,0, 0,0, 0,0, 1.0f);
    gemm_nt<true ><<<gg, 256, SMB>>>(Xc, WkT, Kм, DIM, DIM, DIM, DIM, 1, 0,0, 0,0, 0,0, 1.0f);
    gemm_nt<true ><<<gg, 256, SMB>>>(Xc, WvT, V,  DIM, DIM, DIM, DIM, 1, 0,0, 0,0, 0,0, 1.0f);

    // V -> Vt  [b,h,d,s]
    dim3 tgV(HD/32, SEQ/32, BATCH*NH);
    transpose_z<<<tgV, tb>>>(V, Vt, DIM, SEQ, NH,
                             (long long)HD, (long long)SEQ*DIM,
                             (long long)HD*SEQ, (long long)NH*HD*SEQ, 0);

    // scores: per (b,h)  P[2048,2048] = Q_bh @ K_bh^T * scale
    dim3 gs(SEQ/128, SEQ/128, BATCH*NH);
    gemm_nt<false><<<gs, 256, SMB>>>(Q, Kм, P, HD, DIM, DIM, SEQ,
        NH, (long long)HD, (long long)SEQ*DIM,
            (long long)HD, (long long)SEQ*DIM,
        (long long)SEQ*SEQ, (long long)NH*(long long)SEQ*SEQ,
        0.08838834764831845f /* 1/sqrt(128) */);

    softmax_rows_rna<<<BATCH*NH*SEQ, 256>>>(P);

    // PV: per (b,h)  O_bh[2048,128] = P_bh @ Vt_bh^T(NT)
    dim3 gpv(HD/128, SEQ/128, BATCH*NH);
    gemm_nt<true ><<<gpv, 256, SMB>>>(P, Vt, O, SEQ, SEQ, SEQ, DIM,
        NH, (long long)SEQ*SEQ, (long long)NH*(long long)SEQ*SEQ,
            (long long)HD*SEQ,  (long long)NH*HD*SEQ,
            (long long)HD,      (long long)SEQ*DIM,
        1.0f);

    // out projection: Y = O @ Wo^T(NT)
    gemm_nt<false><<<gg, 256, SMB>>>(O, WoT, Y, DIM, DIM, DIM, DIM, 1, 0,0, 0,0, 0,0, 1.0f);
}

// round 16
// speedup vs baseline: 1.0023x; 1.0013x over previous
#include <cuda_runtime.h>
#include <cstdint>

#define DIM 2048
#define NH 16
#define HD 128
#define BATCH 2
#define SEQ 2048
#define ROWS_TOT (BATCH*SEQ)   // 4096

// ---------------- scratch (device globals: the sanctioned no-alloc workaround) ----
__device__ float g_Xc [(size_t)ROWS_TOT*DIM];
__device__ float g_WqT[(size_t)DIM*DIM];
__device__ float g_WkT[(size_t)DIM*DIM];
__device__ float g_WvT[(size_t)DIM*DIM];
__device__ float g_WoT[(size_t)DIM*DIM];
__device__ float g_Q  [(size_t)ROWS_TOT*DIM];
__device__ float g_Km [(size_t)ROWS_TOT*DIM];
__device__ float g_V  [(size_t)ROWS_TOT*DIM];
__device__ float g_Vt [(size_t)BATCH*NH*HD*SEQ];
__device__ float g_P  [(size_t)BATCH*NH*SEQ*SEQ];   // 512 MB scores/probs
__device__ float g_O  [(size_t)ROWS_TOT*DIM];

// ---------------- helpers ----------------
__device__ __forceinline__ float rna_tf32(float x){
    uint32_t u; asm("cvt.rna.tf32.f32 %0, %1;" : "=r"(u) : "f"(x));
    return __uint_as_float(u);
}
__device__ __forceinline__ void cp16(uint32_t saddr, const void* g){
    asm volatile("cp.async.cg.shared.global [%0], [%1], 16;\n" :: "r"(saddr), "l"(g));
}

// ---------------- generic batched NT GEMM, tf32 mma ----------------
// C[m,n] = alpha * sum_k A[m,k]*B[n,k]; A,B,C row-major with ld strides.
// z = blockIdx.z -> (b = z/H, h = z%H); per-(b,h) base offsets via strides.
// Block tile 128x128, BK=32, 256 threads (8 warps of 64x32), cp.async 2-stage.
template<bool RND>
__global__ void __launch_bounds__(256)
gemm_nt(const float* __restrict__ Ag, const float* __restrict__ Bg,
        float* __restrict__ Cg,
        int K, int lda, int ldb, int ldc,
        int H, long long sAh, long long sAb,
        long long sBh, long long sBb,
        long long sCh, long long sCb, float alpha)
{
    extern __shared__ float smem[];   // 2 stages * (128*36 A + 128*36 B) floats
    const int tid = threadIdx.x;
    const int z  = blockIdx.z;
    const int zb = z / H, zh = z - zb*H;
    const float* A = Ag + (long long)zb*sAb + (long long)zh*sAh;
    const float* B = Bg + (long long)zb*sBb + (long long)zh*sBh;
    float*       C = Cg + (long long)zb*sCb + (long long)zh*sCh;
    const int m0 = blockIdx.y * 128;
    const int n0 = blockIdx.x * 128;

    auto load_stage = [&](int stage, int k0){
        uint32_t sb = (uint32_t)__cvta_generic_to_shared(smem + stage*9216);
        #pragma unroll
        for (int i=0;i<4;i++){
            int f = tid + i*256;
            int row = f >> 3, c4 = (f & 7) << 2;
            cp16(sb + (uint32_t)(row*36 + c4)*4u,
                 A + (long long)(m0+row)*lda + k0 + c4);
        }
        uint32_t sbB = sb + 4608u*4u;
        #pragma unroll
        for (int i=0;i<4;i++){
            int f = tid + i*256;
            int row = f >> 3, c4 = (f & 7) << 2;
            cp16(sbB + (uint32_t)(row*36 + c4)*4u,
                 B + (long long)(n0+row)*ldb + k0 + c4);
        }
    };

    float acc[4][4][4];
    #pragma unroll
    for (int a=0;a<4;a++)
      #pragma unroll
      for (int b=0;b<4;b++)
        #pragma unroll
        for (int c=0;c<4;c++) acc[a][b][c] = 0.f;

    const int wid = tid >> 5, lane = tid & 31;
    const int wm = (wid & 1) * 64, wn = (wid >> 1) * 32;
    const int gid = lane >> 2, tg = lane & 3;

    const int KT = K >> 5;
    load_stage(0, 0);
    asm volatile("cp.async.commit_group;\n");

    for (int kt=0; kt<KT; ++kt){
        if (kt+1 < KT){
            load_stage((kt+1)&1, (kt+1) << 5);
            asm volatile("cp.async.commit_group;\n");
            asm volatile("cp.async.wait_group 1;\n");
        } else {
            asm volatile("cp.async.wait_group 0;\n");
        }
        __syncthreads();
        const float* As = smem + (kt&1)*9216;
        const float* Bs = As + 4608;
        #pragma unroll
        for (int ks=0; ks<4; ks++){
            const int k8 = ks*8;
            uint32_t af[4][4], bf[4][2];
            #pragma unroll
            for (int im=0; im<4; im++){
                int r = wm + im*16 + gid;
                af[im][0] = __float_as_uint(As[ r     *36 + k8 + tg    ]);
                af[im][1] = __float_as_uint(As[(r+8)  *36 + k8 + tg    ]);
                af[im][2] = __float_as_uint(As[ r     *36 + k8 + tg + 4]);
                af[im][3] = __float_as_uint(As[(r+8)  *36 + k8 + tg + 4]);
            }
            #pragma unroll
            for (int jn=0; jn<4; jn++){
                int nn = wn + jn*8 + gid;
                bf[jn][0] = __float_as_uint(Bs[nn*36 + k8 + tg    ]);
                bf[jn][1] = __float_as_uint(Bs[nn*36 + k8 + tg + 4]);
            }
            #pragma unroll
            for (int im=0; im<4; im++)
              #pragma unroll
              for (int jn=0; jn<4; jn++)
                asm volatile(
                  "mma.sync.aligned.m16n8k8.row.col.f32.tf32.tf32.f32 "
                  "{%0,%1,%2,%3}, {%4,%5,%6,%7}, {%8,%9}, {%0,%1,%2,%3};"
                  : "+f"(acc[im][jn][0]), "+f"(acc[im][jn][1]),
                    "+f"(acc[im][jn][2]), "+f"(acc[im][jn][3])
                  : "r"(af[im][0]), "r"(af[im][1]), "r"(af[im][2]), "r"(af[im][3]),
                    "r"(bf[jn][0]), "r"(bf[jn][1]));
        }
        __syncthreads();
    }

    #pragma unroll
    for (int im=0; im<4; im++){
        #pragma unroll
        for (int jn=0; jn<4; jn++){
            long long r0 = m0 + wm + im*16 + gid;
            int cc = n0 + wn + jn*8 + tg*2;
            float v0 = acc[im][jn][0]*alpha, v1 = acc[im][jn][1]*alpha;
            float v2 = acc[im][jn][2]*alpha, v3 = acc[im][jn][3]*alpha;
            if (RND){ v0=rna_tf32(v0); v1=rna_tf32(v1); v2=rna_tf32(v2); v3=rna_tf32(v3); }
            *(float2*)&C[ r0   *ldc + cc] = make_float2(v0, v1);
            *(float2*)&C[(r0+8)*ldc + cc] = make_float2(v2, v3);
        }
    }
}

// ---------------- row softmax (2048 cols), output rounded to tf32 grid ----------
__global__ void softmax_rows_rna(float* __restrict__ P){
    const int n = 2048;
    long long row = blockIdx.x;
    float* p = P + row * (long long)n;
    int tid = threadIdx.x;   // 256
    float v[8];
    float m = -3.0e38f;
    #pragma unroll
    for (int i=0;i<8;i++){ v[i] = p[tid + i*256]; m = fmaxf(m, v[i]); }
    #pragma unroll
    for (int o=16;o;o>>=1) m = fmaxf(m, __shfl_xor_sync(0xffffffffu, m, o));
    __shared__ float red[8];
    if ((tid&31)==0) red[tid>>5] = m;
    __syncthreads();
    float bm = red[0];
    #pragma unroll
    for (int i=1;i<8;i++) bm = fmaxf(bm, red[i]);
    float s = 0.f;
    #pragma unroll
    for (int i=0;i<8;i++){ v[i] = __expf(v[i]-bm); s += v[i]; }
    #pragma unroll
    for (int o=16;o;o>>=1) s += __shfl_xor_sync(0xffffffffu, s, o);
    __syncthreads();
    if ((tid&31)==0) red[tid>>5] = s;
    __syncthreads();
    float bs = 0.f;
    #pragma unroll
    for (int i=0;i<8;i++) bs += red[i];
    float inv = 1.0f / bs;
    #pragma unroll
    for (int i=0;i<8;i++) p[tid + i*256] = rna_tf32(v[i]*inv);
}

// ---------------- tiled transpose (optionally rounding to tf32 grid) -----------
__global__ void transpose_z(const float* __restrict__ In, float* __restrict__ Out,
                            int lda, int ldo, int H,
                            long long siH, long long siB,
                            long long soH, long long soB, int doRnd)
{
    __shared__ float tile[32][33];
    int z = blockIdx.z, b = z / H, h = z - b*H;
    const float* in = In + (long long)b*siB + (long long)h*siH;
    float* out      = Out + (long long)b*soB + (long long)h*soH;
    int c0 = blockIdx.x*32, r0 = blockIdx.y*32;
    int tx = threadIdx.x, ty = threadIdx.y;   // 32 x 8
    #pragma unroll
    for (int i=0;i<32;i+=8)
        tile[ty+i][tx] = in[(long long)(r0+ty+i)*lda + c0+tx];
    __syncthreads();
    #pragma unroll
    for (int i=0;i<32;i+=8){
        float vv = tile[tx][ty+i];
        out[(long long)(c0+ty+i)*ldo + r0+tx] = doRnd ? rna_tf32(vv) : vv;
    }
}

// ---------------- rounded copy ----------------
__global__ void rna_copy(const float* __restrict__ in, float* __restrict__ out, long long n){
    long long i = (long long)blockIdx.x*blockDim.x + threadIdx.x;
    if (i < n) out[i] = rna_tf32(in[i]);
}

// ---------------- driver ----------------
extern "C" void kernel_launch(void* const* d_in, const int* in_sizes, int n_in,
                              void* d_out, int out_size)
{
    (void)in_sizes; (void)n_in; (void)out_size;
    const float* x  = (const float*)d_in[0];
    const float* Wq = (const float*)d_in[1];
    const float* Wk = (const float*)d_in[2];
    const float* Wv = (const float*)d_in[3];
    const float* Wo = (const float*)d_in[4];
    float* Y = (float*)d_out;

    float *Xc,*WqT,*WkT,*WvT,*WoT,*Q,*Kм,*V,*Vt,*P,*O;
    cudaGetSymbolAddress((void**)&Xc,  g_Xc);
    cudaGetSymbolAddress((void**)&WqT, g_WqT);
    cudaGetSymbolAddress((void**)&WkT, g_WkT);
    cudaGetSymbolAddress((void**)&WvT, g_WvT);
    cudaGetSymbolAddress((void**)&WoT, g_WoT);
    cudaGetSymbolAddress((void**)&Q,   g_Q);
    cudaGetSymbolAddress((void**)&Kм,  g_Km);
    cudaGetSymbolAddress((void**)&V,   g_V);
    cudaGetSymbolAddress((void**)&Vt,  g_Vt);
    cudaGetSymbolAddress((void**)&P,   g_P);
    cudaGetSymbolAddress((void**)&O,   g_O);

    const int SMB = 73728;  // 2 stages * (128*36*2 tiles) * 4B
    cudaFuncSetAttribute(gemm_nt<true>,  cudaFuncAttributeMaxDynamicSharedMemorySize, SMB);
    cudaFuncSetAttribute(gemm_nt<false>, cudaFuncAttributeMaxDynamicSharedMemorySize, SMB);

    const long long nX = (long long)ROWS_TOT*DIM;
    rna_copy<<<(int)((nX+255)/256), 256>>>(x, Xc, nX);

    dim3 tb(32,8);
    dim3 tgW(DIM/32, DIM/32, 1);
    transpose_z<<<tgW, tb>>>(Wq, WqT, DIM, DIM, 1, 0,0,0,0, 1);
    transpose_z<<<tgW, tb>>>(Wk, WkT, DIM, DIM, 1, 0,0,0,0, 1);
    transpose_z<<<tgW, tb>>>(Wv, WvT, DIM, DIM, 1, 0,0,0,0, 1);
    transpose_z<<<tgW, tb>>>(Wo, WoT, DIM, DIM, 1, 0,0,0,0, 1);

    // QKV projections: [4096,2048] = Xc @ W^T(NT)
    dim3 gg(DIM/128, ROWS_TOT/128, 1);
    gemm_nt<true ><<<gg, 256, SMB>>>(Xc, WqT, Q,  DIM, DIM, DIM, DIM, 1, 0,0, 0,0, 0,0, 1.0f);
    gemm_nt<true ><<<gg, 256, SMB>>>(Xc, WkT, Kм, DIM, DIM, DIM, DIM, 1, 0,0, 0,0, 0,0, 1.0f);
    gemm_nt<true ><<<gg, 256, SMB>>>(Xc, WvT, V,  DIM, DIM, DIM, DIM, 1, 0,0, 0,0, 0,0, 1.0f);

    // V -> Vt  [b,h,d,s]
    dim3 tgV(HD/32, SEQ/32, BATCH*NH);
    transpose_z<<<tgV, tb>>>(V, Vt, DIM, SEQ, NH,
                             (long long)HD, (long long)SEQ*DIM,
                             (long long)HD*SEQ, (long long)NH*HD*SEQ, 0);

    // scores: per (b,h)  P[2048,2048] = Q_bh @ K_bh^T * scale
    dim3 gs(SEQ/128, SEQ/128, BATCH*NH);
    gemm_nt<false><<<gs, 256, SMB>>>(Q, Kм, P, HD, DIM, DIM, SEQ,
        NH, (long long)HD, (long long)SEQ*DIM,
            (long long)HD, (long long)SEQ*DIM,
        (long long)SEQ*SEQ, (long long)NH*(long long)SEQ*SEQ,
        0.08838834764831845f /* 1/sqrt(128) */);

    softmax_rows_rna<<<BATCH*NH*SEQ, 256>>>(P);

    // PV: per (b,h)  O_bh[2048,128] = P_bh @ Vt_bh^T(NT)
    dim3 gpv(HD/128, SEQ/128, BATCH*NH);
    gemm_nt<true ><<<gpv, 256, SMB>>>(P, Vt, O, SEQ, SEQ, SEQ, DIM,
        NH, (long long)SEQ*SEQ, (long long)NH*(long long)SEQ*SEQ,
            (long long)HD*SEQ,  (long long)NH*HD*SEQ,
            (long long)HD,      (long long)SEQ*DIM,
        1.0f);

    // out projection: Y = O @ Wo^T(NT)
    gemm_nt<false><<<gg, 256, SMB>>>(O, WoT, Y, DIM, DIM, DIM, DIM, 1, 0,0, 0,0, 0,0, 1.0f);
}